// round 1
// baseline (speedup 1.0000x reference)
#include <cuda_runtime.h>

// Fused LIF step: i_in = x@w_in + z@w_rec (fp32, K=256), then elementwise
// spike/leak dynamics. GEMM uses packed fma.rn.f32x2 with K-pairing
// (even/odd partial sums per 64-bit lane pair, folded at the end), so no
// operand duplication is needed and FFMA issue count is halved.

typedef unsigned long long ull;

#define TBX   256      // threads per CTA
#define MROWS 128      // batch rows per CTA
#define NCOLS 128      // output columns (n_rec)
#define KSTG  16       // K per stage
#define NSTG  16       // 256 / 16
#define STRD  20       // smem row stride (floats): 16B-aligned, conflict-free LDS.128

__device__ __forceinline__ ull pk2(float lo, float hi) {
    ull r; asm("mov.b64 %0, {%1, %2};" : "=l"(r) : "f"(lo), "f"(hi)); return r;
}
__device__ __forceinline__ void upk2(ull p, float& lo, float& hi) {
    asm("mov.b64 {%0, %1}, %2;" : "=f"(lo), "=f"(hi) : "l"(p));
}
__device__ __forceinline__ void ffma2(ull& d, ull a, ull b) {
    asm("fma.rn.f32x2 %0, %1, %2, %0;" : "+l"(d) : "l"(a), "l"(b));
}

__global__ __launch_bounds__(TBX, 1)
void lif_fused_kernel(const float* __restrict__ gx,
                      const float* __restrict__ gz,
                      const float* __restrict__ gv,
                      const float* __restrict__ gt,
                      const float* __restrict__ gwin,
                      const float* __restrict__ gwrec,
                      float* __restrict__ out,
                      int B, long long out_elems)
{
    __shared__ float a_s[2][MROWS][STRD];   // A tile: [row][k], 16 k used
    __shared__ float w_s[2][NCOLS][STRD];   // W tile transposed: [col][k]

    const int tid = threadIdx.x;
    const int tx  = tid & 15;               // col group: cols tx + 16*i
    const int ty  = tid >> 4;               // row group: rows 8*ty .. 8*ty+7
    const int r0  = ty << 3;
    const long long browg = (long long)blockIdx.x * MROWS;

    // A-tile load mapping: 2 float4 per thread per stage (128 rows x 16 k)
    const int a_row0 = tid >> 2;            // 0..63
    const int a_row1 = (tid + TBX) >> 2;    // 64..127
    const int a_kc   = (tid & 3) << 2;      // 0,4,8,12
    // W-tile load mapping: 2 float4 per thread per stage (16 k x 128 cols)
    const int w_k0 = tid >> 5;              // 0..7
    const int w_k1 = (tid + TBX) >> 5;      // 8..15
    const int w_c  = (tid & 31) << 2;       // 0..124

    // 8x8 micro-tile; each acc is f32x2: lane-lo = even-k partials, hi = odd-k
    ull acc[8][8];
#pragma unroll
    for (int r = 0; r < 8; r++)
#pragma unroll
        for (int i = 0; i < 8; i++) acc[r][i] = 0ull;

    float4 pa0, pa1, pw0, pw1;

    auto prefetch = [&](int s) {
        const float* Asrc = (s < 8) ? gx : gz;
        const float* Wsrc = (s < 8) ? gwin : gwrec;
        const int kl = (s & 7) * KSTG;
        pa0 = *(const float4*)&Asrc[(browg + a_row0) * NCOLS + kl + a_kc];
        pa1 = *(const float4*)&Asrc[(browg + a_row1) * NCOLS + kl + a_kc];
        pw0 = *(const float4*)&Wsrc[(long long)(kl + w_k0) * NCOLS + w_c];
        pw1 = *(const float4*)&Wsrc[(long long)(kl + w_k1) * NCOLS + w_c];
    };
    auto commit = [&](int buf) {
        *(float4*)&a_s[buf][a_row0][a_kc] = pa0;
        *(float4*)&a_s[buf][a_row1][a_kc] = pa1;
        // transpose W into [col][k]
        w_s[buf][w_c + 0][w_k0] = pw0.x;
        w_s[buf][w_c + 1][w_k0] = pw0.y;
        w_s[buf][w_c + 2][w_k0] = pw0.z;
        w_s[buf][w_c + 3][w_k0] = pw0.w;
        w_s[buf][w_c + 0][w_k1] = pw1.x;
        w_s[buf][w_c + 1][w_k1] = pw1.y;
        w_s[buf][w_c + 2][w_k1] = pw1.z;
        w_s[buf][w_c + 3][w_k1] = pw1.w;
    };

    prefetch(0);
    commit(0);
    __syncthreads();

    for (int s = 0; s < NSTG; s++) {
        const int buf = s & 1;
        if (s + 1 < NSTG) prefetch(s + 1);   // LDG latency overlaps compute

#pragma unroll
        for (int kq = 0; kq < 4; kq++) {     // 4 k-values per iteration
            ull wp[8][2];
#pragma unroll
            for (int i = 0; i < 8; i++) {
                float4 wv = *(const float4*)&w_s[buf][tx + (i << 4)][kq << 2];
                wp[i][0] = pk2(wv.x, wv.y);  // (W[2kp][c], W[2kp+1][c])
                wp[i][1] = pk2(wv.z, wv.w);
            }
#pragma unroll
            for (int r = 0; r < 8; r++) {
                float4 av = *(const float4*)&a_s[buf][r0 + r][kq << 2];
                ull ap0 = pk2(av.x, av.y);   // (A[r][2kp], A[r][2kp+1])
                ull ap1 = pk2(av.z, av.w);
#pragma unroll
                for (int i = 0; i < 8; i++) {
                    ffma2(acc[r][i], ap0, wp[i][0]);
                    ffma2(acc[r][i], ap1, wp[i][1]);
                }
            }
        }

        if (s + 1 < NSTG) {
            commit((s + 1) & 1);   // buffer of stage s-1; its readers passed last sync
            __syncthreads();
        }
    }

    // ---- fused elementwise epilogue ----
    const float L2D = -0.07400058144377693f;   // log2(0.95)
    const long long NB = (long long)B * NCOLS;
    const bool has_t = (out_elems >= 3 * NB);

#pragma unroll
    for (int r = 0; r < 8; r++) {
        const long long rowoff = (browg + r0 + r) * NCOLS;
#pragma unroll
        for (int i = 0; i < 8; i++) {
            const long long idx = rowoff + tx + (i << 4);
            float lo, hi; upk2(acc[r][i], lo, hi);
            float iin = lo + hi;

            float zv = gz[idx];
            float vv = gv[idx];
            float tv = gt[idx];

            float h  = (iin != 0.0f) ? 1.0f : 0.0f;
            float nt = tv + (1.0f - h);              // t + (h != 1)
            float nv = vv * (1.0f - zv);             // reset on spike
            if (!(vv > -1.0f)) nv -= (vv + 1.0f);    // clamp below -1
            nv *= exp2f(h * (nt + 1.0f) * L2D);      // decay ** (h*(nt+1))
            nt *= (1.0f - h);                        // reset counter if active
            nv += iin;
            float nz = (nv > 0.4f) ? 1.0f : 0.0f;    // spike((nv-THR)/THR)

            out[idx]          = nz;                  // stack[0] = new_z
            out[NB + idx]     = nv;                  // stack[1] = new_v
            if (has_t) out[2 * NB + idx] = nt;       // new_t
        }
    }
}

extern "C" void kernel_launch(void* const* d_in, const int* in_sizes, int n_in,
                              void* d_out, int out_size)
{
    const float* x     = (const float*)d_in[0];
    const float* z     = (const float*)d_in[1];
    const float* v     = (const float*)d_in[2];
    const float* t     = (const float*)d_in[3];
    const float* w_in  = (const float*)d_in[4];
    const float* w_rec = (const float*)d_in[5];

    const int B = in_sizes[0] / NCOLS;       // 131072
    const int grid = B / MROWS;              // 1024 CTAs

    lif_fused_kernel<<<grid, TBX>>>(x, z, v, t, w_in, w_rec,
                                    (float*)d_out, B, (long long)out_size);
}

// round 3
// speedup vs baseline: 2.2463x; 2.2463x over previous
#include <cuda_runtime.h>
#include <cuda_fp16.h>
#include <stdint.h>

// Fused LIF step, sm_103-portable tensor path (mma.sync HMMA, no tcgen05/TMA).
//   i_in = x@w_in + z@w_rec via error-free fp16 splitting:
//     x = x0+x1 (fp16 2-split), w_in*64 = w0+w1, w_rec*64 = r0+r1
//     i_in*64 = x0@w0 + x0@w1 + x1@w0 + z@r0 + z@r1   (z exact in fp16)
//   Weight scaling by 64 keeps split residuals out of fp16 subnormal floor.
//   fp32 accumulate -> error ~5e-8 abs (fp32-class). 5 HMMA product-GEMMs.
// Epilogue: acc -> smem fp32 staging -> coalesced elementwise LIF dynamics.

typedef unsigned long long u64;
typedef uint32_t u32;

#define TBX 256
#define WSCALE 64.0f
#define INV_WSCALE 0.015625f

// fp16 tile byte offsets (each 128x128 fp16 = 32KB, XOR-swizzled)
#define T_X0 0u
#define T_X1 32768u
#define T_Z  65536u
#define T_W0 98304u
#define T_W1 131072u
#define T_R0 163840u
#define T_R1 196608u
#define SMEM_BYTES 229376
// fp32 i_in staging aliases X0+X1 (64KB), written only after all MMAs.

static __device__ __forceinline__ u32 s2u(const void* p){
  u32 a; asm("{ .reg .u64 t; cvta.to.shared.u64 t, %1; cvt.u32.u64 %0, t; }":"=r"(a):"l"(p)); return a;
}
// fp16 tile: row = 256B = 16 segs of 16B; XOR low 3 seg bits with row&7.
static __device__ __forceinline__ u32 swz16(int r, int c){
  return (u32)((r<<8) + ((((c>>3) ^ (r&7)) & 15)<<4) + ((c&7)<<1));
}
// fp32 staging: row = 512B = 32 segs of 16B; same XOR trick.
static __device__ __forceinline__ u32 swz32(int r, int c){
  return (u32)((r<<9) + ((((c>>2) ^ (r&7)) & 31)<<4) + ((c&3)<<2));
}
static __device__ __forceinline__ void sts64(u32 a, u32 lo, u32 hi){
  asm volatile("st.shared.v2.u32 [%0], {%1,%2};"::"r"(a),"r"(lo),"r"(hi));
}
static __device__ __forceinline__ void stsf2(u32 a, float x, float y){
  asm volatile("st.shared.v2.f32 [%0], {%1,%2};"::"r"(a),"f"(x),"f"(y));
}
static __device__ __forceinline__ u32 h2u(__half2 h){ return *reinterpret_cast<u32*>(&h); }

// 2-way fp16 split of 4 scaled floats: primary -> a0, residual -> a1.
static __device__ __forceinline__ void split_store4(u32 a0, u32 a1, float4 f, float s){
  float x0=f.x*s, x1=f.y*s, x2=f.z*s, x3=f.w*s;
  __half h00=__float2half_rn(x0), h01=__float2half_rn(x1);
  __half h02=__float2half_rn(x2), h03=__float2half_rn(x3);
  sts64(a0, h2u(__halves2half2(h00,h01)), h2u(__halves2half2(h02,h03)));
  __half h10=__float2half_rn(x0-__half2float(h00));
  __half h11=__float2half_rn(x1-__half2float(h01));
  __half h12=__float2half_rn(x2-__half2float(h02));
  __half h13=__float2half_rn(x3-__half2float(h03));
  sts64(a1, h2u(__halves2half2(h10,h11)), h2u(__halves2half2(h12,h13)));
}

static __device__ __forceinline__ void ldsm4(u32 addr, u32& r0, u32& r1, u32& r2, u32& r3){
  asm volatile("ldmatrix.sync.aligned.m8n8.x4.shared.b16 {%0,%1,%2,%3}, [%4];"
               : "=r"(r0),"=r"(r1),"=r"(r2),"=r"(r3) : "r"(addr));
}
static __device__ __forceinline__ void ldsm4t(u32 addr, u32& r0, u32& r1, u32& r2, u32& r3){
  asm volatile("ldmatrix.sync.aligned.m8n8.x4.trans.shared.b16 {%0,%1,%2,%3}, [%4];"
               : "=r"(r0),"=r"(r1),"=r"(r2),"=r"(r3) : "r"(addr));
}
static __device__ __forceinline__ void mma16816(float* c, const u32* a, u32 b0, u32 b1){
  asm volatile("mma.sync.aligned.m16n8k16.row.col.f32.f16.f16.f32 "
               "{%0,%1,%2,%3}, {%4,%5,%6,%7}, {%8,%9}, {%0,%1,%2,%3};"
               : "+f"(c[0]),"+f"(c[1]),"+f"(c[2]),"+f"(c[3])
               : "r"(a[0]),"r"(a[1]),"r"(a[2]),"r"(a[3]), "r"(b0),"r"(b1));
}

__global__ __launch_bounds__(TBX, 1)
void lif_hmma_kernel(const float* __restrict__ gx, const float* __restrict__ gz,
                     const float* __restrict__ gv, const float* __restrict__ gt,
                     const float* __restrict__ gwin, const float* __restrict__ gwrec,
                     float* __restrict__ out, int Btot, long long out_elems)
{
  extern __shared__ __align__(1024) char smem[];
  const u32 sb = s2u(smem);
  const int tid = threadIdx.x;
  const int wid = tid >> 5, lid = tid & 31;
  const long long browg = (long long)blockIdx.x * 128;

  // ===== producers: load + split to fp16 tiles =====
  {
    const float4* X4 = reinterpret_cast<const float4*>(gx) + browg*32;
    const float4* Z4 = reinterpret_cast<const float4*>(gz) + browg*32;
    const float4* Wi = reinterpret_cast<const float4*>(gwin);
    const float4* Wr = reinterpret_cast<const float4*>(gwrec);
#pragma unroll
    for (int q = 0; q < 16; q++) {
      int e = q*TBX + tid;                 // 4096 float4 = 128x128
      int r = e >> 5, c4 = (e & 31) << 2;
      u32 so = swz16(r, c4);
      // x split (unscaled)
      split_store4(sb + T_X0 + so, sb + T_X1 + so, X4[e], 1.0f);
      // weights split (scaled by 64)
      split_store4(sb + T_W0 + so, sb + T_W1 + so, Wi[e], WSCALE);
      split_store4(sb + T_R0 + so, sb + T_R1 + so, Wr[e], WSCALE);
      // z exact fp16
      float4 zv = Z4[e];
      sts64(sb + T_Z + so,
            h2u(__floats2half2_rn(zv.x, zv.y)),
            h2u(__floats2half2_rn(zv.z, zv.w)));
    }
  }
  __syncthreads();

  // ===== 5 product-GEMMs, warp tile 32x64, fp32 acc =====
  const int mrow = (wid & 3) << 5;
  const int ncol = (wid >> 2) << 6;
  // ldmatrix lane address components
  const int a_r  = (lid & 7) + ((lid >> 3) & 1) * 8;   // row within m16
  const int a_k8 = (lid >> 4) * 8;                      // k col half
  const int b_k  = (lid & 7) + ((lid >> 3) & 1) * 8;   // k row within k16
  const int b_n8 = (lid >> 4) * 8;                      // n col half

  float acc[2][8][4];
#pragma unroll
  for (int mt = 0; mt < 2; mt++)
#pragma unroll
    for (int j = 0; j < 8; j++)
#pragma unroll
      for (int k = 0; k < 4; k++) acc[mt][j][k] = 0.0f;

#pragma unroll
  for (int p = 0; p < 5; p++) {
    const u32 abase = sb + (p==0 ? T_X0 : p==1 ? T_X0 : p==2 ? T_X1 : T_Z);
    const u32 bbase = sb + (p==0 ? T_W0 : p==1 ? T_W1 : p==2 ? T_W0 : p==3 ? T_R0 : T_R1);
#pragma unroll 2
    for (int ks = 0; ks < 8; ks++) {
      const int kb = ks << 4;
      u32 a[2][4];
#pragma unroll
      for (int mt = 0; mt < 2; mt++)
        ldsm4(abase + swz16(mrow + mt*16 + a_r, kb + a_k8),
              a[mt][0], a[mt][1], a[mt][2], a[mt][3]);
      u32 b[4][4];   // [n16 block][{n8a.b0, n8a.b1, n8b.b0, n8b.b1}]
#pragma unroll
      for (int nb = 0; nb < 4; nb++)
        ldsm4t(bbase + swz16(kb + b_k, ncol + nb*16 + b_n8),
               b[nb][0], b[nb][1], b[nb][2], b[nb][3]);
#pragma unroll
      for (int mt = 0; mt < 2; mt++)
#pragma unroll
        for (int j = 0; j < 8; j++)
          mma16816(acc[mt][j], a[mt], b[j>>1][(j&1)*2], b[j>>1][(j&1)*2+1]);
    }
  }

  __syncthreads();   // all ldmatrix reads of X0/X1 done before staging overwrites

  // ===== acc -> fp32 i_in staging (aliases X0/X1), scaled by 1/64 =====
  {
    const int rq = lid >> 2, cq = (lid & 3) << 1;
#pragma unroll
    for (int mt = 0; mt < 2; mt++) {
      const int r0 = mrow + mt*16 + rq;
#pragma unroll
      for (int j = 0; j < 8; j++) {
        const int c = ncol + j*8 + cq;
        stsf2(sb + swz32(r0,     c), acc[mt][j][0]*INV_WSCALE, acc[mt][j][1]*INV_WSCALE);
        stsf2(sb + swz32(r0 + 8, c), acc[mt][j][2]*INV_WSCALE, acc[mt][j][3]*INV_WSCALE);
      }
    }
  }
  __syncthreads();

  // ===== coalesced fused LIF epilogue =====
  const float L2D = -0.07400058144377693f;   // log2(0.95) : decay = 1 - 1/20
  const long long NB = (long long)Btot * 128;
  const bool has_t = (out_elems >= 3*NB);
#pragma unroll
  for (int q = 0; q < 16; q++) {
    int e4  = ((q << 8) + tid) << 2;         // element index 0..16380 step 4
    int row = e4 >> 7, col = e4 & 127;
    float4 iv;
    asm volatile("ld.shared.v4.f32 {%0,%1,%2,%3}, [%4];"
                 : "=f"(iv.x),"=f"(iv.y),"=f"(iv.z),"=f"(iv.w)
                 : "r"(sb + swz32(row, col)));
    u32 zl, zh;
    asm volatile("ld.shared.v2.u32 {%0,%1}, [%2];" : "=r"(zl),"=r"(zh)
                 : "r"(sb + T_Z + swz16(row, col)));
    __half2 zp0 = *reinterpret_cast<__half2*>(&zl);
    __half2 zp1 = *reinterpret_cast<__half2*>(&zh);
    float zf[4] = {__half2float(__low2half(zp0)), __half2float(__high2half(zp0)),
                   __half2float(__low2half(zp1)), __half2float(__high2half(zp1))};
    long long gi = browg*128 + e4;
    float4 vv = reinterpret_cast<const float4*>(gv)[gi>>2];
    float4 tv = reinterpret_cast<const float4*>(gt)[gi>>2];
    float ia[4] = {iv.x, iv.y, iv.z, iv.w};
    float va[4] = {vv.x, vv.y, vv.z, vv.w};
    float ta[4] = {tv.x, tv.y, tv.z, tv.w};
    float nzo[4], nvo[4], nto[4];
#pragma unroll
    for (int j = 0; j < 4; j++) {
      float iin = ia[j];
      float h  = (iin != 0.0f) ? 1.0f : 0.0f;
      float nt = ta[j] + (1.0f - h);
      float nv = va[j] * (1.0f - zf[j]);
      if (!(va[j] > -1.0f)) nv -= (va[j] + 1.0f);
      nv *= exp2f(h * (nt + 1.0f) * L2D);
      nt *= (1.0f - h);
      nv += iin;
      nzo[j] = (nv > 0.4f) ? 1.0f : 0.0f;
      nvo[j] = nv; nto[j] = nt;
    }
    float4 o;
    o.x=nzo[0]; o.y=nzo[1]; o.z=nzo[2]; o.w=nzo[3];
    *reinterpret_cast<float4*>(&out[gi]) = o;
    o.x=nvo[0]; o.y=nvo[1]; o.z=nvo[2]; o.w=nvo[3];
    *reinterpret_cast<float4*>(&out[NB + gi]) = o;
    if (has_t) {
      o.x=nto[0]; o.y=nto[1]; o.z=nto[2]; o.w=nto[3];
      *reinterpret_cast<float4*>(&out[2*NB + gi]) = o;
    }
  }
}

extern "C" void kernel_launch(void* const* d_in, const int* in_sizes, int n_in,
                              void* d_out, int out_size)
{
  const float* x     = (const float*)d_in[0];
  const float* z     = (const float*)d_in[1];
  const float* v     = (const float*)d_in[2];
  const float* t     = (const float*)d_in[3];
  const float* w_in  = (const float*)d_in[4];
  const float* w_rec = (const float*)d_in[5];

  const int B = in_sizes[0] / 128;       // 131072
  const int grid = B / 128;              // 1024 CTAs

  static int smem_set = 0;
  if (!smem_set) {
    cudaFuncSetAttribute(lif_hmma_kernel,
                         cudaFuncAttributeMaxDynamicSharedMemorySize, SMEM_BYTES);
    smem_set = 1;
  }
  lif_hmma_kernel<<<grid, TBX, SMEM_BYTES>>>(x, z, v, t, w_in, w_rec,
                                             (float*)d_out, B, (long long)out_size);
}